// round 4
// baseline (speedup 1.0000x reference)
#include <cuda_runtime.h>

// Problem-fixed dimensions (from reference: N=100000, E=1600000, D=256, H=128, O=64)
#define NMAX 100000
#define EMAX 1600000
#define DDIM 256
#define HDIM 128
#define ODIM 64

// ---------------- device scratch (static, no allocation) ----------------
__device__ float g_h1 [NMAX*HDIM];   // x @ W1
__device__ float g_g1 [NMAX*HDIM];   // relu(agg_gcn(h1)+b1)
__device__ float g_p1 [NMAX*HDIM];   // relu(agg_ppmi(h1)+b1)
__device__ float g_h2g[NMAX*ODIM];   // g1 @ W2
__device__ float g_h2p[NMAX*ODIM];   // p1 @ W2
__device__ float g_disg[NMAX];       // deg_gcn -> deg^-0.5
__device__ float g_disp[NMAX];       // deg_ppmi -> deg^-0.5
__device__ int   g_cnt   [NMAX];
__device__ int   g_cursor[NMAX];
__device__ int   g_colptr[NMAX+1];
__device__ int   g_src[EMAX];        // CSR (by destination col): source node
__device__ float g_gn [EMAX];        // gcn  norm per CSR slot
__device__ float g_pn [EMAX];        // ppmi norm per CSR slot
__device__ int   g_bsums[128];

// ---------------- init (re-run every launch: graph replays!) ----------------
__global__ void k_init(int n) {
    int i = blockIdx.x * blockDim.x + threadIdx.x;
    if (i < n) {
        g_cnt[i] = 0;
        g_cursor[i] = 0;
        g_disg[i] = 1.0f;   // self-loop weight 1 contributes to degree
        g_disp[i] = 1.0f;
    }
}

// ---------------- degrees + in-degree counts ----------------
// edge_index is int32 on device (JAX x64 is disabled; harness dtypes are
// float32/int32/bf16). Layout: [2, E] -> row = ei[e], col = ei[E + e].
__global__ void k_deg(const int* __restrict__ ei,
                      const float* __restrict__ ppmi, int E) {
    int e = blockIdx.x * blockDim.x + threadIdx.x;
    if (e < E) {
        int r = ei[e];
        int c = ei[E + e];
        atomicAdd(&g_disg[r], 1.0f);
        atomicAdd(&g_disp[r], ppmi[e]);
        atomicAdd(&g_cnt[c], 1);
    }
}

__global__ void k_rsqrt(int n) {
    int i = blockIdx.x * blockDim.x + threadIdx.x;
    if (i < n) {
        g_disg[i] = rsqrtf(g_disg[i]);
        g_disp[i] = rsqrtf(g_disp[i]);
    }
}

// ---------------- exclusive scan of g_cnt -> g_colptr ----------------
__global__ void k_scan1(int n) {   // blockDim = 1024
    __shared__ int wsum[32];
    int i = blockIdx.x * 1024 + threadIdx.x;
    int v = (i < n) ? g_cnt[i] : 0;
    int x = v;
    #pragma unroll
    for (int o = 1; o < 32; o <<= 1) {
        int y = __shfl_up_sync(0xffffffffu, x, o);
        if ((threadIdx.x & 31) >= o) x += y;
    }
    if ((threadIdx.x & 31) == 31) wsum[threadIdx.x >> 5] = x;
    __syncthreads();
    if (threadIdx.x < 32) {
        int s = wsum[threadIdx.x];
        #pragma unroll
        for (int o = 1; o < 32; o <<= 1) {
            int y = __shfl_up_sync(0xffffffffu, s, o);
            if (threadIdx.x >= o) s += y;
        }
        wsum[threadIdx.x] = s;
    }
    __syncthreads();
    int base = (threadIdx.x >= 32) ? wsum[(threadIdx.x >> 5) - 1] : 0;
    int incl = base + x;
    if (i < n) g_colptr[i] = incl - v;               // block-local exclusive
    if (threadIdx.x == 1023) g_bsums[blockIdx.x] = incl;
}

__global__ void k_scan2(int nb) {  // single block, blockDim = 128, nb <= 128
    __shared__ int s[128];
    int t = threadIdx.x;
    s[t] = (t < nb) ? g_bsums[t] : 0;
    __syncthreads();
    for (int o = 1; o < 128; o <<= 1) {
        int y = (t >= o) ? s[t - o] : 0;
        __syncthreads();
        s[t] += y;
        __syncthreads();
    }
    if (t < nb) g_bsums[t] = (t > 0) ? s[t - 1] : 0;  // exclusive block offsets
}

__global__ void k_scan3(int n, int E) {  // blockDim = 1024
    int i = blockIdx.x * 1024 + threadIdx.x;
    if (i < n) g_colptr[i] += g_bsums[blockIdx.x];
    if (i == 0) g_colptr[n] = E;
}

// ---------------- CSR fill (by destination) ----------------
__global__ void k_fill(const int* __restrict__ ei,
                       const float* __restrict__ ppmi, int E) {
    int e = blockIdx.x * blockDim.x + threadIdx.x;
    if (e >= E) return;
    int r = ei[e];
    int c = ei[E + e];
    int pos = g_colptr[c] + atomicAdd(&g_cursor[c], 1);
    g_src[pos] = r;
    g_gn[pos] = g_disg[r] * g_disg[c];
    g_pn[pos] = g_disp[r] * ppmi[e] * g_disp[c];
}

// ---------------- register-tiled fp32 GEMM body ----------------
// C[M x BN] = A[M x K] * B[K x BN], BN == full output width (col0 = 0)
template <int BM, int BN, int BK, int TM, int TN, int K>
__device__ __forceinline__ void sgemm_body(const float* __restrict__ A,
                                           const float* __restrict__ B,
                                           float* __restrict__ C, int M) {
    constexpr int NT = (BM / TM) * (BN / TN);
    __shared__ __align__(16) float As[BK][BM];
    __shared__ __align__(16) float Bs[BK][BN];
    const int tid = threadIdx.x;
    const int row0 = blockIdx.x * BM;
    const int tx = tid % (BN / TN);
    const int ty = tid / (BN / TN);

    float acc[TM][TN];
    #pragma unroll
    for (int i = 0; i < TM; i++)
        #pragma unroll
        for (int j = 0; j < TN; j++) acc[i][j] = 0.0f;

    for (int k0 = 0; k0 < K; k0 += BK) {
        #pragma unroll
        for (int idx = tid; idx < BM * BK; idx += NT) {
            int r = idx / BK, c = idx % BK;
            int gr = row0 + r;
            As[c][r] = (gr < M) ? A[(size_t)gr * K + k0 + c] : 0.0f;
        }
        #pragma unroll
        for (int idx = tid; idx < BK * BN; idx += NT) {
            int r = idx / BN, c = idx % BN;
            Bs[r][c] = B[(size_t)(k0 + r) * BN + c];
        }
        __syncthreads();
        #pragma unroll
        for (int kk = 0; kk < BK; kk++) {
            float a[TM], b[TN];
            #pragma unroll
            for (int i = 0; i < TM; i += 4) {
                float4 a4 = *reinterpret_cast<const float4*>(&As[kk][ty * TM + i]);
                a[i] = a4.x; a[i + 1] = a4.y; a[i + 2] = a4.z; a[i + 3] = a4.w;
            }
            #pragma unroll
            for (int j = 0; j < TN; j += 4) {
                float4 b4 = *reinterpret_cast<const float4*>(&Bs[kk][tx * TN + j]);
                b[j] = b4.x; b[j + 1] = b4.y; b[j + 2] = b4.z; b[j + 3] = b4.w;
            }
            #pragma unroll
            for (int i = 0; i < TM; i++)
                #pragma unroll
                for (int j = 0; j < TN; j++) acc[i][j] += a[i] * b[j];
        }
        __syncthreads();
    }
    #pragma unroll
    for (int i = 0; i < TM; i++) {
        int gr = row0 + ty * TM + i;
        if (gr < M) {
            #pragma unroll
            for (int j = 0; j < TN; j += 4) {
                float4 o4 = make_float4(acc[i][j], acc[i][j + 1], acc[i][j + 2], acc[i][j + 3]);
                *reinterpret_cast<float4*>(&C[(size_t)gr * BN + tx * TN + j]) = o4;
            }
        }
    }
}

__global__ void k_gemm1(const float* __restrict__ A, const float* __restrict__ B, int M) {
    sgemm_body<64, 128, 16, 8, 4, DDIM>(A, B, g_h1, M);   // 256 threads
}

__global__ void k_gemm2(const float* __restrict__ B, int M) {
    const float* A = blockIdx.y ? g_p1 : g_g1;
    float* C = blockIdx.y ? g_h2p : g_h2g;
    sgemm_body<64, 64, 16, 4, 4, HDIM>(A, B, C, M);       // 256 threads
}

// ---------------- layer-1 aggregation: warp per node, both branches fused ----------------
__global__ void k_agg1(const float* __restrict__ b1, int n) {
    int node = (blockIdx.x * blockDim.x + threadIdx.x) >> 5;
    int lane = threadIdx.x & 31;
    if (node >= n) return;
    int s0 = g_colptr[node], s1 = g_colptr[node + 1];
    float4 ag = make_float4(0, 0, 0, 0);
    float4 ap = make_float4(0, 0, 0, 0);
    for (int e = s0; e < s1; e++) {
        int s = g_src[e];
        float gn = g_gn[e], pn = g_pn[e];
        float4 v = *reinterpret_cast<const float4*>(&g_h1[(size_t)s * HDIM + lane * 4]);
        ag.x += gn * v.x; ag.y += gn * v.y; ag.z += gn * v.z; ag.w += gn * v.w;
        ap.x += pn * v.x; ap.y += pn * v.y; ap.z += pn * v.z; ap.w += pn * v.w;
    }
    // self loop: norm = dis[i]^2 (weight 1 both branches)
    float dg = g_disg[node]; dg *= dg;
    float dp = g_disp[node]; dp *= dp;
    float4 v = *reinterpret_cast<const float4*>(&g_h1[(size_t)node * HDIM + lane * 4]);
    ag.x += dg * v.x; ag.y += dg * v.y; ag.z += dg * v.z; ag.w += dg * v.w;
    ap.x += dp * v.x; ap.y += dp * v.y; ap.z += dp * v.z; ap.w += dp * v.w;
    float4 bb = *reinterpret_cast<const float4*>(&b1[lane * 4]);
    ag.x = fmaxf(ag.x + bb.x, 0.f); ag.y = fmaxf(ag.y + bb.y, 0.f);
    ag.z = fmaxf(ag.z + bb.z, 0.f); ag.w = fmaxf(ag.w + bb.w, 0.f);
    ap.x = fmaxf(ap.x + bb.x, 0.f); ap.y = fmaxf(ap.y + bb.y, 0.f);
    ap.z = fmaxf(ap.z + bb.z, 0.f); ap.w = fmaxf(ap.w + bb.w, 0.f);
    *reinterpret_cast<float4*>(&g_g1[(size_t)node * HDIM + lane * 4]) = ag;
    *reinterpret_cast<float4*>(&g_p1[(size_t)node * HDIM + lane * 4]) = ap;
}

// ---------------- layer-2 aggregation + attention combine: warp per node ----------------
__global__ void k_agg2_combine(const float* __restrict__ b2,
                               const float* __restrict__ dw,
                               const float* __restrict__ db,
                               float* __restrict__ out, int n) {
    int node = (blockIdx.x * blockDim.x + threadIdx.x) >> 5;
    int lane = threadIdx.x & 31;
    if (node >= n) return;
    int s0 = g_colptr[node], s1 = g_colptr[node + 1];
    float2 ag = make_float2(0, 0);
    float2 ap = make_float2(0, 0);
    for (int e = s0; e < s1; e++) {
        int s = g_src[e];
        float gn = g_gn[e], pn = g_pn[e];
        float2 vg = *reinterpret_cast<const float2*>(&g_h2g[(size_t)s * ODIM + lane * 2]);
        float2 vp = *reinterpret_cast<const float2*>(&g_h2p[(size_t)s * ODIM + lane * 2]);
        ag.x += gn * vg.x; ag.y += gn * vg.y;
        ap.x += pn * vp.x; ap.y += pn * vp.y;
    }
    float dg = g_disg[node]; dg *= dg;
    float dp = g_disp[node]; dp *= dp;
    float2 vg = *reinterpret_cast<const float2*>(&g_h2g[(size_t)node * ODIM + lane * 2]);
    float2 vp = *reinterpret_cast<const float2*>(&g_h2p[(size_t)node * ODIM + lane * 2]);
    ag.x += dg * vg.x; ag.y += dg * vg.y;
    ap.x += dp * vp.x; ap.y += dp * vp.y;
    float2 bb = *reinterpret_cast<const float2*>(&b2[lane * 2]);
    ag.x += bb.x; ag.y += bb.y;
    ap.x += bb.x; ap.y += bb.y;
    // logits: dot(feat, dense_w) via warp reduction
    float2 w = *reinterpret_cast<const float2*>(&dw[lane * 2]);
    float lg = ag.x * w.x + ag.y * w.y;
    float lp = ap.x * w.x + ap.y * w.y;
    #pragma unroll
    for (int o = 16; o; o >>= 1) {
        lg += __shfl_xor_sync(0xffffffffu, lg, o);
        lp += __shfl_xor_sync(0xffffffffu, lp, o);
    }
    float bd = db[0];
    lg += bd; lp += bd;
    float m = fmaxf(lg, lp);
    float eg = __expf(lg - m), ep = __expf(lp - m);
    float wg = eg / (eg + ep), wp = 1.0f - wg;
    float2 o2;
    o2.x = wg * ag.x + wp * ap.x;
    o2.y = wg * ag.y + wp * ap.y;
    *reinterpret_cast<float2*>(&out[(size_t)node * ODIM + lane * 2]) = o2;
}

// ---------------- launch ----------------
extern "C" void kernel_launch(void* const* d_in, const int* in_sizes, int n_in,
                              void* d_out, int out_size) {
    const float* x    = (const float*)d_in[0];
    const int*   ei   = (const int*)d_in[1];     // int32 [2, E]
    const float* ppmi = (const float*)d_in[2];
    const float* W1   = (const float*)d_in[3];
    const float* b1   = (const float*)d_in[4];
    const float* W2   = (const float*)d_in[5];
    const float* b2   = (const float*)d_in[6];
    const float* dw   = (const float*)d_in[7];
    const float* db   = (const float*)d_in[8];
    float*       out  = (float*)d_out;

    const int N = in_sizes[0] / DDIM;
    const int E = in_sizes[2];

    const int TB = 256;
    // init + degrees + dis
    k_init<<<(N + TB - 1) / TB, TB>>>(N);
    k_deg<<<(E + TB - 1) / TB, TB>>>(ei, ppmi, E);
    k_rsqrt<<<(N + TB - 1) / TB, TB>>>(N);
    // exclusive scan of counts -> colptr
    int nb = (N + 1023) / 1024;
    k_scan1<<<nb, 1024>>>(N);
    k_scan2<<<1, 128>>>(nb);
    k_scan3<<<nb, 1024>>>(N, E);
    // CSR fill with per-edge norms
    k_fill<<<(E + TB - 1) / TB, TB>>>(ei, ppmi, E);
    // layer 1: GEMM + fused two-branch aggregation (+bias, relu)
    k_gemm1<<<(N + 63) / 64, 256>>>(x, W1, N);
    k_agg1<<<(N * 32 + TB - 1) / TB, TB>>>(b1, N);
    // layer 2: two GEMMs (grid.y selects branch) + fused aggregation + attention combine
    {
        dim3 grid((N + 63) / 64, 2);
        k_gemm2<<<grid, 256>>>(W2, N);
    }
    k_agg2_combine<<<(N * 32 + TB - 1) / TB, TB>>>(b2, dw, db, out, N);
}

// round 7
// speedup vs baseline: 1.2536x; 1.2536x over previous
#include <cuda_runtime.h>
#include <cuda_bf16.h>
#include <cstdint>

// Problem-fixed dimensions (N=100000, E=1600000, D=256, H=128, O=64)
#define NMAX 100000
#define EMAX 1600000
#define DDIM 256
#define HDIM 128
#define ODIM 64

// ============================ warp-MMA helpers (plain sm_103 PTX) ============================
__device__ __forceinline__ uint32_t smem_to_u32(const void* p) {
    uint32_t a;
    asm("{ .reg .u64 t; cvta.to.shared.u64 t, %1; cvt.u32.u64 %0, t; }" : "=r"(a) : "l"(p));
    return a;
}
__device__ __forceinline__ void ldmx4(uint32_t* r, uint32_t addr) {
    asm volatile("ldmatrix.sync.aligned.m8n8.x4.shared.b16 {%0,%1,%2,%3}, [%4];"
        : "=r"(r[0]), "=r"(r[1]), "=r"(r[2]), "=r"(r[3]) : "r"(addr));
}
__device__ __forceinline__ void mma16816(float* d, const uint32_t* a, const uint32_t* b) {
    asm volatile("mma.sync.aligned.m16n8k16.row.col.f32.bf16.bf16.f32 "
        "{%0,%1,%2,%3}, {%4,%5,%6,%7}, {%8,%9}, {%0,%1,%2,%3};"
        : "+f"(d[0]), "+f"(d[1]), "+f"(d[2]), "+f"(d[3])
        : "r"(a[0]), "r"(a[1]), "r"(a[2]), "r"(a[3]), "r"(b[0]), "r"(b[1]));
}

// ---------------- device scratch (static, no allocation) ----------------
__device__ float g_h1 [NMAX*HDIM];                 // x @ W1 (fp32)
__device__ float g_h2g[NMAX*ODIM];                 // g1 @ W2
__device__ float g_h2p[NMAX*ODIM];                 // p1 @ W2
__device__ __nv_bfloat16 g_xhi[NMAX*DDIM];         // bf16 split of x
__device__ __nv_bfloat16 g_xlo[NMAX*DDIM];
__device__ __nv_bfloat16 g_g1h[NMAX*HDIM];         // bf16 splits of relu-agg outputs
__device__ __nv_bfloat16 g_g1l[NMAX*HDIM];
__device__ __nv_bfloat16 g_p1h[NMAX*HDIM];
__device__ __nv_bfloat16 g_p1l[NMAX*HDIM];
__device__ __nv_bfloat16 g_w1h[HDIM*DDIM];         // W1^T splits: [n=128][k=256]
__device__ __nv_bfloat16 g_w1l[HDIM*DDIM];
__device__ __nv_bfloat16 g_w2h[ODIM*HDIM];         // W2^T splits: [n=64][k=128]
__device__ __nv_bfloat16 g_w2l[ODIM*HDIM];
__device__ float g_disg[NMAX];
__device__ float g_disp[NMAX];
__device__ int   g_cnt   [NMAX];
__device__ int   g_cursor[NMAX];
__device__ int   g_colptr[NMAX+1];
__device__ int   g_src[EMAX];
__device__ float g_gn [EMAX];
__device__ float g_pn [EMAX];
__device__ int   g_bsums[128];

// ---------------- init (re-run every graph replay) ----------------
__global__ void k_init(int n) {
    int i = blockIdx.x * blockDim.x + threadIdx.x;
    if (i < n) { g_cnt[i] = 0; g_cursor[i] = 0; g_disg[i] = 1.0f; g_disp[i] = 1.0f; }
}

__global__ void k_deg(const int* __restrict__ ei, const float* __restrict__ ppmi, int E) {
    int e = blockIdx.x * blockDim.x + threadIdx.x;
    if (e < E) {
        int r = ei[e]; int c = ei[E + e];
        atomicAdd(&g_disg[r], 1.0f);
        atomicAdd(&g_disp[r], ppmi[e]);
        atomicAdd(&g_cnt[c], 1);
    }
}

__global__ void k_rsqrt(int n) {
    int i = blockIdx.x * blockDim.x + threadIdx.x;
    if (i < n) { g_disg[i] = rsqrtf(g_disg[i]); g_disp[i] = rsqrtf(g_disp[i]); }
}

// ---------------- exclusive scan of g_cnt -> g_colptr ----------------
__global__ void k_scan1(int n) {
    __shared__ int wsum[32];
    int i = blockIdx.x * 1024 + threadIdx.x;
    int v = (i < n) ? g_cnt[i] : 0;
    int x = v;
    #pragma unroll
    for (int o = 1; o < 32; o <<= 1) {
        int y = __shfl_up_sync(0xffffffffu, x, o);
        if ((threadIdx.x & 31) >= o) x += y;
    }
    if ((threadIdx.x & 31) == 31) wsum[threadIdx.x >> 5] = x;
    __syncthreads();
    if (threadIdx.x < 32) {
        int s = wsum[threadIdx.x];
        #pragma unroll
        for (int o = 1; o < 32; o <<= 1) {
            int y = __shfl_up_sync(0xffffffffu, s, o);
            if (threadIdx.x >= o) s += y;
        }
        wsum[threadIdx.x] = s;
    }
    __syncthreads();
    int base = (threadIdx.x >= 32) ? wsum[(threadIdx.x >> 5) - 1] : 0;
    int incl = base + x;
    if (i < n) g_colptr[i] = incl - v;
    if (threadIdx.x == 1023) g_bsums[blockIdx.x] = incl;
}

__global__ void k_scan2(int nb) {
    __shared__ int s[128];
    int t = threadIdx.x;
    s[t] = (t < nb) ? g_bsums[t] : 0;
    __syncthreads();
    for (int o = 1; o < 128; o <<= 1) {
        int y = (t >= o) ? s[t - o] : 0;
        __syncthreads();
        s[t] += y;
        __syncthreads();
    }
    if (t < nb) g_bsums[t] = (t > 0) ? s[t - 1] : 0;
}

__global__ void k_scan3(int n, int E) {
    int i = blockIdx.x * 1024 + threadIdx.x;
    if (i < n) g_colptr[i] += g_bsums[blockIdx.x];
    if (i == 0) g_colptr[n] = E;
}

__global__ void k_fill(const int* __restrict__ ei, const float* __restrict__ ppmi, int E) {
    int e = blockIdx.x * blockDim.x + threadIdx.x;
    if (e >= E) return;
    int r = ei[e]; int c = ei[E + e];
    int pos = g_colptr[c] + atomicAdd(&g_cursor[c], 1);
    g_src[pos] = r;
    g_gn[pos] = g_disg[r] * g_disg[c];
    g_pn[pos] = g_disp[r] * ppmi[e] * g_disp[c];
}

// ---------------- bf16 split prep ----------------
__global__ void k_splitX(const float* __restrict__ x, int n) {   // n = N*DDIM
    int i = blockIdx.x * blockDim.x + threadIdx.x;
    if (i < n) {
        float v = x[i];
        __nv_bfloat16 h = __float2bfloat16(v);
        g_xhi[i] = h;
        g_xlo[i] = __float2bfloat16(v - __bfloat162float(h));
    }
}
__global__ void k_splitW1(const float* __restrict__ W1) {        // [256,128] -> T splits [128][256]
    int i = blockIdx.x * blockDim.x + threadIdx.x;
    if (i < DDIM * HDIM) {
        int k = i >> 7, nn = i & 127;
        float v = W1[k * HDIM + nn];
        __nv_bfloat16 h = __float2bfloat16(v);
        g_w1h[nn * DDIM + k] = h;
        g_w1l[nn * DDIM + k] = __float2bfloat16(v - __bfloat162float(h));
    }
}
__global__ void k_splitW2(const float* __restrict__ W2) {        // [128,64] -> T splits [64][128]
    int i = blockIdx.x * blockDim.x + threadIdx.x;
    if (i < HDIM * ODIM) {
        int k = i >> 6, nn = i & 63;
        float v = W2[k * ODIM + nn];
        __nv_bfloat16 h = __float2bfloat16(v);
        g_w2h[nn * HDIM + k] = h;
        g_w2l[nn * HDIM + k] = __float2bfloat16(v - __bfloat162float(h));
    }
}

// ---------------- SMEM tile fill: ROWS x 64 bf16, padded stride 72 bf16 (144 B) ----------------
template <int ROWS>
__device__ __forceinline__ void fill_pad(char* smem, int dst_off,
                                         const uint4* __restrict__ src,  // 8 bf16 per uint4
                                         long long first_row, int stride_u4, int k0_u4,
                                         int nvalid, int tid) {
    for (int u = tid; u < ROWS * 8; u += 256) {
        int r = u >> 3, c = u & 7;
        uint4 v = make_uint4(0, 0, 0, 0);
        if (r < nvalid) v = src[(size_t)(first_row + r) * stride_u4 + k0_u4 + c];
        *reinterpret_cast<uint4*>(smem + dst_off + r * 144 + c * 16) = v;
    }
}

// ---------------- GEMM1: h1[M,128] = x[M,256] @ W1 via bf16x3 mma.sync ----------------
// SMEM: Ahi/Alo 128x(64+8) bf16 = 18432 B each; Bhi/Blo same. Total 73728 B.
static constexpr int G1_SMEM = 4 * 18432;
__global__ void __launch_bounds__(256) k_gemm1_tc(int M) {
    extern __shared__ char smem[];
    uint32_t sb = smem_to_u32(smem);
    const int tid = threadIdx.x, wid = tid >> 5, lane = tid & 31;
    const int warpM = wid & 3, warpN = wid >> 2;          // 4 x 2 warps
    const int AHI = 0, ALO = 18432, BHI = 36864, BLO = 55296;

    long long row0 = (long long)blockIdx.x * 128;
    int nvalid = (int)((M - row0 < 128) ? (M - row0) : 128);
    const uint4* xh = reinterpret_cast<const uint4*>(g_xhi);
    const uint4* xl = reinterpret_cast<const uint4*>(g_xlo);
    const uint4* wh = reinterpret_cast<const uint4*>(g_w1h);
    const uint4* wl = reinterpret_cast<const uint4*>(g_w1l);

    float acc[2][8][4];
    #pragma unroll
    for (int i = 0; i < 2; i++)
        #pragma unroll
        for (int j = 0; j < 8; j++)
            #pragma unroll
            for (int k = 0; k < 4; k++) acc[i][j][k] = 0.0f;

    // ldmatrix per-lane address components
    const int a_r = (lane & 7) + ((lane & 8) ? 8 : 0);    // A: row within 16-tile
    const int a_c = (lane & 16) ? 8 : 0;                  // A: col half
    const int b_r = (lane & 7) + ((lane & 16) ? 8 : 0);   // B: row within 16 (two n-tiles)
    const int b_c = (lane & 8) ? 8 : 0;                   // B: col half

    #pragma unroll 1
    for (int c = 0; c < 4; c++) {                         // K chunks of 64 (K=256)
        int k0u = c * 8;
        if (c) __syncthreads();
        fill_pad<128>(smem, AHI, xh, row0, 32, k0u, nvalid, tid);
        fill_pad<128>(smem, ALO, xl, row0, 32, k0u, nvalid, tid);
        fill_pad<128>(smem, BHI, wh, 0, 32, k0u, 128, tid);
        fill_pad<128>(smem, BLO, wl, 0, 32, k0u, 128, tid);
        __syncthreads();
        #pragma unroll
        for (int k16 = 0; k16 < 4; k16++) {
            int kc = k16 * 16;
            uint32_t ah[2][4], al[2][4];
            #pragma unroll
            for (int mt = 0; mt < 2; mt++) {
                uint32_t off = (uint32_t)((warpM * 32 + mt * 16 + a_r) * 144 + (kc + a_c) * 2);
                ldmx4(ah[mt], sb + AHI + off);
                ldmx4(al[mt], sb + ALO + off);
            }
            uint32_t bh[8][2], bl[8][2];
            #pragma unroll
            for (int np = 0; np < 4; np++) {
                uint32_t off = (uint32_t)((warpN * 64 + np * 16 + b_r) * 144 + (kc + b_c) * 2);
                uint32_t t4[4];
                ldmx4(t4, sb + BHI + off);
                bh[2*np][0] = t4[0]; bh[2*np][1] = t4[1];
                bh[2*np+1][0] = t4[2]; bh[2*np+1][1] = t4[3];
                ldmx4(t4, sb + BLO + off);
                bl[2*np][0] = t4[0]; bl[2*np][1] = t4[1];
                bl[2*np+1][0] = t4[2]; bl[2*np+1][1] = t4[3];
            }
            #pragma unroll
            for (int mt = 0; mt < 2; mt++)
                #pragma unroll
                for (int nt = 0; nt < 8; nt++) {
                    mma16816(acc[mt][nt], ah[mt], bh[nt]);
                    mma16816(acc[mt][nt], ah[mt], bl[nt]);
                    mma16816(acc[mt][nt], al[mt], bh[nt]);
                }
        }
    }
    // epilogue
    int g = lane >> 2, t = lane & 3;
    #pragma unroll
    for (int mt = 0; mt < 2; mt++) {
        long long r0 = row0 + warpM * 32 + mt * 16 + g;
        #pragma unroll
        for (int nt = 0; nt < 8; nt++) {
            int col = warpN * 64 + nt * 8 + t * 2;
            if (r0 < M)
                *reinterpret_cast<float2*>(&g_h1[r0 * HDIM + col]) =
                    make_float2(acc[mt][nt][0], acc[mt][nt][1]);
            if (r0 + 8 < M)
                *reinterpret_cast<float2*>(&g_h1[(r0 + 8) * HDIM + col]) =
                    make_float2(acc[mt][nt][2], acc[mt][nt][3]);
        }
    }
}

// ---------------- GEMM2: h2{g,p}[M,64] = {g1,p1}[M,128] @ W2 via bf16x3 mma.sync ----------------
// SMEM: Ahi/Alo 128x72 = 18432 each; Bhi/Blo 64x72 = 9216 each. Total 55296 B.
static constexpr int G2_SMEM = 2 * 18432 + 2 * 9216;
__global__ void __launch_bounds__(256) k_gemm2_tc(int M) {
    extern __shared__ char smem[];
    uint32_t sb = smem_to_u32(smem);
    const int tid = threadIdx.x, wid = tid >> 5, lane = tid & 31;
    const int warpM = wid & 3, warpN = wid >> 2;          // 4 x 2 warps, warp tile 32x32
    const int AHI = 0, ALO = 18432, BHI = 36864, BLO = 46080;

    long long row0 = (long long)blockIdx.x * 128;
    int nvalid = (int)((M - row0 < 128) ? (M - row0) : 128);
    const uint4* ah4 = reinterpret_cast<const uint4*>(blockIdx.y ? g_p1h : g_g1h);
    const uint4* al4 = reinterpret_cast<const uint4*>(blockIdx.y ? g_p1l : g_g1l);
    const uint4* wh = reinterpret_cast<const uint4*>(g_w2h);
    const uint4* wl = reinterpret_cast<const uint4*>(g_w2l);
    float* C = blockIdx.y ? g_h2p : g_h2g;

    float acc[2][4][4];
    #pragma unroll
    for (int i = 0; i < 2; i++)
        #pragma unroll
        for (int j = 0; j < 4; j++)
            #pragma unroll
            for (int k = 0; k < 4; k++) acc[i][j][k] = 0.0f;

    const int a_r = (lane & 7) + ((lane & 8) ? 8 : 0);
    const int a_c = (lane & 16) ? 8 : 0;
    const int b_r = (lane & 7) + ((lane & 16) ? 8 : 0);
    const int b_c = (lane & 8) ? 8 : 0;

    #pragma unroll 1
    for (int c = 0; c < 2; c++) {                         // K chunks of 64 (K=128)
        int k0u = c * 8;
        if (c) __syncthreads();
        fill_pad<128>(smem, AHI, ah4, row0, 16, k0u, nvalid, tid);
        fill_pad<128>(smem, ALO, al4, row0, 16, k0u, nvalid, tid);
        fill_pad<64>(smem, BHI, wh, 0, 16, k0u, 64, tid);
        fill_pad<64>(smem, BLO, wl, 0, 16, k0u, 64, tid);
        __syncthreads();
        #pragma unroll
        for (int k16 = 0; k16 < 4; k16++) {
            int kc = k16 * 16;
            uint32_t ah[2][4], al[2][4];
            #pragma unroll
            for (int mt = 0; mt < 2; mt++) {
                uint32_t off = (uint32_t)((warpM * 32 + mt * 16 + a_r) * 144 + (kc + a_c) * 2);
                ldmx4(ah[mt], sb + AHI + off);
                ldmx4(al[mt], sb + ALO + off);
            }
            uint32_t bh[4][2], bl[4][2];
            #pragma unroll
            for (int np = 0; np < 2; np++) {
                uint32_t off = (uint32_t)((warpN * 32 + np * 16 + b_r) * 144 + (kc + b_c) * 2);
                uint32_t t4[4];
                ldmx4(t4, sb + BHI + off);
                bh[2*np][0] = t4[0]; bh[2*np][1] = t4[1];
                bh[2*np+1][0] = t4[2]; bh[2*np+1][1] = t4[3];
                ldmx4(t4, sb + BLO + off);
                bl[2*np][0] = t4[0]; bl[2*np][1] = t4[1];
                bl[2*np+1][0] = t4[2]; bl[2*np+1][1] = t4[3];
            }
            #pragma unroll
            for (int mt = 0; mt < 2; mt++)
                #pragma unroll
                for (int nt = 0; nt < 4; nt++) {
                    mma16816(acc[mt][nt], ah[mt], bh[nt]);
                    mma16816(acc[mt][nt], ah[mt], bl[nt]);
                    mma16816(acc[mt][nt], al[mt], bh[nt]);
                }
        }
    }
    int g = lane >> 2, t = lane & 3;
    #pragma unroll
    for (int mt = 0; mt < 2; mt++) {
        long long r0 = row0 + warpM * 32 + mt * 16 + g;
        #pragma unroll
        for (int nt = 0; nt < 4; nt++) {
            int col = warpN * 32 + nt * 8 + t * 2;
            if (r0 < M)
                *reinterpret_cast<float2*>(&C[r0 * ODIM + col]) =
                    make_float2(acc[mt][nt][0], acc[mt][nt][1]);
            if (r0 + 8 < M)
                *reinterpret_cast<float2*>(&C[(r0 + 8) * ODIM + col]) =
                    make_float2(acc[mt][nt][2], acc[mt][nt][3]);
        }
    }
}

// ---------------- layer-1 aggregation: warp/node, both branches, emits bf16 splits ----------------
__device__ __forceinline__ void split_store(__nv_bfloat16* hi, __nv_bfloat16* lo, size_t base, float4 v) {
    __nv_bfloat16 hx = __float2bfloat16(v.x), hy = __float2bfloat16(v.y);
    __nv_bfloat16 hz = __float2bfloat16(v.z), hw = __float2bfloat16(v.w);
    __nv_bfloat162* h2 = reinterpret_cast<__nv_bfloat162*>(hi + base);
    __nv_bfloat162* l2 = reinterpret_cast<__nv_bfloat162*>(lo + base);
    h2[0] = __halves2bfloat162(hx, hy);
    h2[1] = __halves2bfloat162(hz, hw);
    l2[0] = __halves2bfloat162(__float2bfloat16(v.x - __bfloat162float(hx)),
                               __float2bfloat16(v.y - __bfloat162float(hy)));
    l2[1] = __halves2bfloat162(__float2bfloat16(v.z - __bfloat162float(hz)),
                               __float2bfloat16(v.w - __bfloat162float(hw)));
}

__global__ void k_agg1(const float* __restrict__ b1, int n) {
    int node = (blockIdx.x * blockDim.x + threadIdx.x) >> 5;
    int lane = threadIdx.x & 31;
    if (node >= n) return;
    int s0 = g_colptr[node], s1 = g_colptr[node + 1];
    float4 ag = make_float4(0, 0, 0, 0);
    float4 ap = make_float4(0, 0, 0, 0);
    for (int e = s0; e < s1; e++) {
        int s = g_src[e];
        float gn = g_gn[e], pn = g_pn[e];
        float4 v = *reinterpret_cast<const float4*>(&g_h1[(size_t)s * HDIM + lane * 4]);
        ag.x += gn * v.x; ag.y += gn * v.y; ag.z += gn * v.z; ag.w += gn * v.w;
        ap.x += pn * v.x; ap.y += pn * v.y; ap.z += pn * v.z; ap.w += pn * v.w;
    }
    float dg = g_disg[node]; dg *= dg;
    float dp = g_disp[node]; dp *= dp;
    float4 v = *reinterpret_cast<const float4*>(&g_h1[(size_t)node * HDIM + lane * 4]);
    ag.x += dg * v.x; ag.y += dg * v.y; ag.z += dg * v.z; ag.w += dg * v.w;
    ap.x += dp * v.x; ap.y += dp * v.y; ap.z += dp * v.z; ap.w += dp * v.w;
    float4 bb = *reinterpret_cast<const float4*>(&b1[lane * 4]);
    ag.x = fmaxf(ag.x + bb.x, 0.f); ag.y = fmaxf(ag.y + bb.y, 0.f);
    ag.z = fmaxf(ag.z + bb.z, 0.f); ag.w = fmaxf(ag.w + bb.w, 0.f);
    ap.x = fmaxf(ap.x + bb.x, 0.f); ap.y = fmaxf(ap.y + bb.y, 0.f);
    ap.z = fmaxf(ap.z + bb.z, 0.f); ap.w = fmaxf(ap.w + bb.w, 0.f);
    size_t base = (size_t)node * HDIM + lane * 4;
    split_store(g_g1h, g_g1l, base, ag);
    split_store(g_p1h, g_p1l, base, ap);
}

// ---------------- layer-2 aggregation + attention combine ----------------
__global__ void k_agg2_combine(const float* __restrict__ b2,
                               const float* __restrict__ dw,
                               const float* __restrict__ db,
                               float* __restrict__ out, int n) {
    int node = (blockIdx.x * blockDim.x + threadIdx.x) >> 5;
    int lane = threadIdx.x & 31;
    if (node >= n) return;
    int s0 = g_colptr[node], s1 = g_colptr[node + 1];
    float2 ag = make_float2(0, 0);
    float2 ap = make_float2(0, 0);
    for (int e = s0; e < s1; e++) {
        int s = g_src[e];
        float gn = g_gn[e], pn = g_pn[e];
        float2 vg = *reinterpret_cast<const float2*>(&g_h2g[(size_t)s * ODIM + lane * 2]);
        float2 vp = *reinterpret_cast<const float2*>(&g_h2p[(size_t)s * ODIM + lane * 2]);
        ag.x += gn * vg.x; ag.y += gn * vg.y;
        ap.x += pn * vp.x; ap.y += pn * vp.y;
    }
    float dg = g_disg[node]; dg *= dg;
    float dp = g_disp[node]; dp *= dp;
    float2 vg = *reinterpret_cast<const float2*>(&g_h2g[(size_t)node * ODIM + lane * 2]);
    float2 vp = *reinterpret_cast<const float2*>(&g_h2p[(size_t)node * ODIM + lane * 2]);
    ag.x += dg * vg.x; ag.y += dg * vg.y;
    ap.x += dp * vp.x; ap.y += dp * vp.y;
    float2 bb = *reinterpret_cast<const float2*>(&b2[lane * 2]);
    ag.x += bb.x; ag.y += bb.y;
    ap.x += bb.x; ap.y += bb.y;
    float2 w = *reinterpret_cast<const float2*>(&dw[lane * 2]);
    float lg = ag.x * w.x + ag.y * w.y;
    float lp = ap.x * w.x + ap.y * w.y;
    #pragma unroll
    for (int o = 16; o; o >>= 1) {
        lg += __shfl_xor_sync(0xffffffffu, lg, o);
        lp += __shfl_xor_sync(0xffffffffu, lp, o);
    }
    float bd = db[0];
    lg += bd; lp += bd;
    float m = fmaxf(lg, lp);
    float eg = __expf(lg - m), ep = __expf(lp - m);
    float wg = eg / (eg + ep), wp = 1.0f - wg;
    float2 o2;
    o2.x = wg * ag.x + wp * ap.x;
    o2.y = wg * ag.y + wp * ap.y;
    *reinterpret_cast<float2*>(&out[(size_t)node * ODIM + lane * 2]) = o2;
}

// ---------------- launch ----------------
extern "C" void kernel_launch(void* const* d_in, const int* in_sizes, int n_in,
                              void* d_out, int out_size) {
    const float* x    = (const float*)d_in[0];
    const int*   ei   = (const int*)d_in[1];     // int32 [2, E]
    const float* ppmi = (const float*)d_in[2];
    const float* W1   = (const float*)d_in[3];
    const float* b1   = (const float*)d_in[4];
    const float* W2   = (const float*)d_in[5];
    const float* b2   = (const float*)d_in[6];
    const float* dw   = (const float*)d_in[7];
    const float* db   = (const float*)d_in[8];
    float*       out  = (float*)d_out;

    const int N = in_sizes[0] / DDIM;
    const int E = in_sizes[2];

    cudaFuncSetAttribute(k_gemm1_tc, cudaFuncAttributeMaxDynamicSharedMemorySize, G1_SMEM);
    cudaFuncSetAttribute(k_gemm2_tc, cudaFuncAttributeMaxDynamicSharedMemorySize, G2_SMEM);

    const int TB = 256;
    // graph build
    k_init<<<(N + TB - 1) / TB, TB>>>(N);
    k_deg<<<(E + TB - 1) / TB, TB>>>(ei, ppmi, E);
    k_rsqrt<<<(N + TB - 1) / TB, TB>>>(N);
    int nb = (N + 1023) / 1024;
    k_scan1<<<nb, 1024>>>(N);
    k_scan2<<<1, 128>>>(nb);
    k_scan3<<<nb, 1024>>>(N, E);
    k_fill<<<(E + TB - 1) / TB, TB>>>(ei, ppmi, E);
    // bf16 split prep
    k_splitX<<<(N * DDIM + TB - 1) / TB, TB>>>(x, N * DDIM);
    k_splitW1<<<(DDIM * HDIM + TB - 1) / TB, TB>>>(W1);
    k_splitW2<<<(HDIM * ODIM + TB - 1) / TB, TB>>>(W2);
    // layer 1
    int g1 = (N + 127) / 128;
    k_gemm1_tc<<<g1, 256, G1_SMEM>>>(N);
    k_agg1<<<(N * 32 + TB - 1) / TB, TB>>>(b1, N);
    // layer 2 (grid.y selects branch)
    dim3 grid2(g1, 2);
    k_gemm2_tc<<<grid2, 256, G2_SMEM>>>(N);
    k_agg2_combine<<<(N * 32 + TB - 1) / TB, TB>>>(b2, dw, db, out, N);
}

// round 8
// speedup vs baseline: 1.6609x; 1.3249x over previous
#include <cuda_runtime.h>
#include <cuda_bf16.h>
#include <cstdint>

// Problem-fixed dimensions (N=100000, E=1600000, D=256, H=128, O=64)
#define NMAX 100000
#define EMAX 1600000
#define DDIM 256
#define HDIM 128
#define ODIM 64

// ============================ warp-MMA helpers (plain sm_103 PTX) ============================
__device__ __forceinline__ uint32_t smem_to_u32(const void* p) {
    uint32_t a;
    asm("{ .reg .u64 t; cvta.to.shared.u64 t, %1; cvt.u32.u64 %0, t; }" : "=r"(a) : "l"(p));
    return a;
}
__device__ __forceinline__ void ldmx4(uint32_t* r, uint32_t addr) {
    asm volatile("ldmatrix.sync.aligned.m8n8.x4.shared.b16 {%0,%1,%2,%3}, [%4];"
        : "=r"(r[0]), "=r"(r[1]), "=r"(r[2]), "=r"(r[3]) : "r"(addr));
}
__device__ __forceinline__ void mma16816(float* d, const uint32_t* a, const uint32_t* b) {
    asm volatile("mma.sync.aligned.m16n8k16.row.col.f32.bf16.bf16.f32 "
        "{%0,%1,%2,%3}, {%4,%5,%6,%7}, {%8,%9}, {%0,%1,%2,%3};"
        : "+f"(d[0]), "+f"(d[1]), "+f"(d[2]), "+f"(d[3])
        : "r"(a[0]), "r"(a[1]), "r"(a[2]), "r"(a[3]), "r"(b[0]), "r"(b[1]));
}
__device__ __forceinline__ uint32_t bpack(__nv_bfloat16 a, __nv_bfloat16 b) {
    __nv_bfloat162 t = __halves2bfloat162(a, b);
    return *reinterpret_cast<uint32_t*>(&t);
}

// ---------------- device scratch (static, no allocation) ----------------
__device__ float g_h1 [NMAX*HDIM];                 // x @ W1 (fp32)
__device__ float g_h2 [NMAX*2*ODIM];               // interleaved: [node][0:64)=g branch, [64:128)=p branch
__device__ __nv_bfloat16 g_g1h[NMAX*HDIM];         // bf16 splits of relu-agg outputs
__device__ __nv_bfloat16 g_g1l[NMAX*HDIM];
__device__ __nv_bfloat16 g_p1h[NMAX*HDIM];
__device__ __nv_bfloat16 g_p1l[NMAX*HDIM];
__device__ __nv_bfloat16 g_w1h[HDIM*DDIM];         // W1^T splits: [n=128][k=256]
__device__ __nv_bfloat16 g_w1l[HDIM*DDIM];
__device__ __nv_bfloat16 g_w2h[ODIM*HDIM];         // W2^T splits: [n=64][k=128]
__device__ __nv_bfloat16 g_w2l[ODIM*HDIM];
__device__ float g_disg[NMAX];
__device__ float g_disp[NMAX];
__device__ int   g_cnt   [NMAX];
__device__ int   g_cursor[NMAX];
__device__ int   g_colptr[NMAX+1];
__device__ int   g_src[EMAX];
__device__ float g_gn [EMAX];
__device__ float g_pn [EMAX];
__device__ int   g_bsums[128];

// ---------------- static stream/event for capture-legal fork (created at load, before
// the harness's memory baselines; falls back to single-stream if creation fails) ----------
static cudaStream_t g_s2 = nullptr;
static cudaEvent_t  g_ev0 = nullptr, g_ev1 = nullptr;
namespace {
struct ForkInit {
    ForkInit() {
        if (cudaStreamCreateWithFlags(&g_s2, cudaStreamNonBlocking) != cudaSuccess) g_s2 = nullptr;
        if (cudaEventCreateWithFlags(&g_ev0, cudaEventDisableTiming) != cudaSuccess) g_ev0 = nullptr;
        if (cudaEventCreateWithFlags(&g_ev1, cudaEventDisableTiming) != cudaSuccess) g_ev1 = nullptr;
    }
};
ForkInit g_forkinit;
}

// ---------------- init (re-run every graph replay) ----------------
__global__ void k_init(int n) {
    int i = blockIdx.x * blockDim.x + threadIdx.x;
    if (i < n) { g_cnt[i] = 0; g_cursor[i] = 0; g_disg[i] = 1.0f; g_disp[i] = 1.0f; }
}

__global__ void k_deg(const int* __restrict__ ei, const float* __restrict__ ppmi, int E) {
    int e = blockIdx.x * blockDim.x + threadIdx.x;
    if (e < E) {
        int r = ei[e]; int c = ei[E + e];
        atomicAdd(&g_disg[r], 1.0f);
        atomicAdd(&g_disp[r], ppmi[e]);
        atomicAdd(&g_cnt[c], 1);
    }
}

__global__ void k_rsqrt(int n) {
    int i = blockIdx.x * blockDim.x + threadIdx.x;
    if (i < n) { g_disg[i] = rsqrtf(g_disg[i]); g_disp[i] = rsqrtf(g_disp[i]); }
}

// ---------------- exclusive scan of g_cnt -> g_colptr ----------------
__global__ void k_scan1(int n) {
    __shared__ int wsum[32];
    int i = blockIdx.x * 1024 + threadIdx.x;
    int v = (i < n) ? g_cnt[i] : 0;
    int x = v;
    #pragma unroll
    for (int o = 1; o < 32; o <<= 1) {
        int y = __shfl_up_sync(0xffffffffu, x, o);
        if ((threadIdx.x & 31) >= o) x += y;
    }
    if ((threadIdx.x & 31) == 31) wsum[threadIdx.x >> 5] = x;
    __syncthreads();
    if (threadIdx.x < 32) {
        int s = wsum[threadIdx.x];
        #pragma unroll
        for (int o = 1; o < 32; o <<= 1) {
            int y = __shfl_up_sync(0xffffffffu, s, o);
            if (threadIdx.x >= o) s += y;
        }
        wsum[threadIdx.x] = s;
    }
    __syncthreads();
    int base = (threadIdx.x >= 32) ? wsum[(threadIdx.x >> 5) - 1] : 0;
    int incl = base + x;
    if (i < n) g_colptr[i] = incl - v;
    if (threadIdx.x == 1023) g_bsums[blockIdx.x] = incl;
}

__global__ void k_scan2(int nb) {
    __shared__ int s[128];
    int t = threadIdx.x;
    s[t] = (t < nb) ? g_bsums[t] : 0;
    __syncthreads();
    for (int o = 1; o < 128; o <<= 1) {
        int y = (t >= o) ? s[t - o] : 0;
        __syncthreads();
        s[t] += y;
        __syncthreads();
    }
    if (t < nb) g_bsums[t] = (t > 0) ? s[t - 1] : 0;
}

__global__ void k_scan3(int n, int E) {
    int i = blockIdx.x * 1024 + threadIdx.x;
    if (i < n) g_colptr[i] += g_bsums[blockIdx.x];
    if (i == 0) g_colptr[n] = E;
}

__global__ void k_fill(const int* __restrict__ ei, const float* __restrict__ ppmi, int E) {
    int e = blockIdx.x * blockDim.x + threadIdx.x;
    if (e >= E) return;
    int r = ei[e]; int c = ei[E + e];
    int pos = g_colptr[c] + atomicAdd(&g_cursor[c], 1);
    g_src[pos] = r;
    g_gn[pos] = g_disg[r] * g_disg[c];
    g_pn[pos] = g_disp[r] * ppmi[e] * g_disp[c];
}

// ---------------- weight split prep (tiny) ----------------
__global__ void k_splitW1(const float* __restrict__ W1) {        // [256,128] -> T splits [128][256]
    int i = blockIdx.x * blockDim.x + threadIdx.x;
    if (i < DDIM * HDIM) {
        int k = i >> 7, nn = i & 127;
        float v = W1[k * HDIM + nn];
        __nv_bfloat16 h = __float2bfloat16(v);
        g_w1h[nn * DDIM + k] = h;
        g_w1l[nn * DDIM + k] = __float2bfloat16(v - __bfloat162float(h));
    }
}
__global__ void k_splitW2(const float* __restrict__ W2) {        // [128,64] -> T splits [64][128]
    int i = blockIdx.x * blockDim.x + threadIdx.x;
    if (i < HDIM * ODIM) {
        int k = i >> 6, nn = i & 63;
        float v = W2[k * ODIM + nn];
        __nv_bfloat16 h = __float2bfloat16(v);
        g_w2h[nn * HDIM + k] = h;
        g_w2l[nn * HDIM + k] = __float2bfloat16(v - __bfloat162float(h));
    }
}

// ---------------- SMEM tile fill: ROWS x 64 bf16, padded row stride 144 B ----------------
template <int ROWS>
__device__ __forceinline__ void fill_pad(char* smem, int dst_off,
                                         const uint4* __restrict__ src,  // 8 bf16 per uint4
                                         long long first_row, int stride_u4, int k0_u4,
                                         int nvalid, int tid) {
    for (int u = tid; u < ROWS * 8; u += 256) {
        int r = u >> 3, c = u & 7;
        uint4 v = make_uint4(0, 0, 0, 0);
        if (r < nvalid) v = src[(size_t)(first_row + r) * stride_u4 + k0_u4 + c];
        *reinterpret_cast<uint4*>(smem + dst_off + r * 144 + c * 16) = v;
    }
}

// fp32 source -> hi/lo bf16 tiles in one pass (ROWS x 64 cols)
template <int ROWS>
__device__ __forceinline__ void fill_split(char* smem, int hi_off, int lo_off,
                                           const float4* __restrict__ src,  // 4 fp32 per float4
                                           long long first_row, int stride_f4, int k0_f4,
                                           int nvalid, int tid) {
    for (int u = tid; u < ROWS * 16; u += 256) {
        int r = u >> 4, c = u & 15;
        float4 v = make_float4(0, 0, 0, 0);
        if (r < nvalid) v = src[(size_t)(first_row + r) * stride_f4 + k0_f4 + c];
        __nv_bfloat16 hx = __float2bfloat16(v.x), hy = __float2bfloat16(v.y);
        __nv_bfloat16 hz = __float2bfloat16(v.z), hw = __float2bfloat16(v.w);
        uint2 hi2 = make_uint2(bpack(hx, hy), bpack(hz, hw));
        uint2 lo2 = make_uint2(
            bpack(__float2bfloat16(v.x - __bfloat162float(hx)), __float2bfloat16(v.y - __bfloat162float(hy))),
            bpack(__float2bfloat16(v.z - __bfloat162float(hz)), __float2bfloat16(v.w - __bfloat162float(hw))));
        int bo = r * 144 + c * 8;
        *reinterpret_cast<uint2*>(smem + hi_off + bo) = hi2;
        *reinterpret_cast<uint2*>(smem + lo_off + bo) = lo2;
    }
}

// ---------------- GEMM1: h1[M,128] = x[M,256] @ W1 via bf16x3 mma.sync ----------------
static constexpr int G1_SMEM = 4 * 18432;
__global__ void __launch_bounds__(256) k_gemm1_tc(const float* __restrict__ x, int M) {
    extern __shared__ char smem[];
    uint32_t sb = smem_to_u32(smem);
    const int tid = threadIdx.x, wid = tid >> 5, lane = tid & 31;
    const int warpM = wid & 3, warpN = wid >> 2;          // 4 x 2 warps
    const int AHI = 0, ALO = 18432, BHI = 36864, BLO = 55296;

    long long row0 = (long long)blockIdx.x * 128;
    int nvalid = (int)((M - row0 < 128) ? (M - row0) : 128);
    const float4* x4 = reinterpret_cast<const float4*>(x);
    const uint4* wh = reinterpret_cast<const uint4*>(g_w1h);
    const uint4* wl = reinterpret_cast<const uint4*>(g_w1l);

    float acc[2][8][4];
    #pragma unroll
    for (int i = 0; i < 2; i++)
        #pragma unroll
        for (int j = 0; j < 8; j++)
            #pragma unroll
            for (int k = 0; k < 4; k++) acc[i][j][k] = 0.0f;

    const int a_r = (lane & 7) + ((lane & 8) ? 8 : 0);
    const int a_c = (lane & 16) ? 8 : 0;
    const int b_r = (lane & 7) + ((lane & 16) ? 8 : 0);
    const int b_c = (lane & 8) ? 8 : 0;

    #pragma unroll 1
    for (int c = 0; c < 4; c++) {                         // K chunks of 64 (K=256)
        if (c) __syncthreads();
        fill_split<128>(smem, AHI, ALO, x4, row0, 64, c * 16, nvalid, tid);
        fill_pad<128>(smem, BHI, wh, 0, 32, c * 8, 128, tid);
        fill_pad<128>(smem, BLO, wl, 0, 32, c * 8, 128, tid);
        __syncthreads();
        #pragma unroll
        for (int k16 = 0; k16 < 4; k16++) {
            int kc = k16 * 16;
            uint32_t ah[2][4], al[2][4];
            #pragma unroll
            for (int mt = 0; mt < 2; mt++) {
                uint32_t off = (uint32_t)((warpM * 32 + mt * 16 + a_r) * 144 + (kc + a_c) * 2);
                ldmx4(ah[mt], sb + AHI + off);
                ldmx4(al[mt], sb + ALO + off);
            }
            uint32_t bh[8][2], bl[8][2];
            #pragma unroll
            for (int np = 0; np < 4; np++) {
                uint32_t off = (uint32_t)((warpN * 64 + np * 16 + b_r) * 144 + (kc + b_c) * 2);
                uint32_t t4[4];
                ldmx4(t4, sb + BHI + off);
                bh[2*np][0] = t4[0]; bh[2*np][1] = t4[1];
                bh[2*np+1][0] = t4[2]; bh[2*np+1][1] = t4[3];
                ldmx4(t4, sb + BLO + off);
                bl[2*np][0] = t4[0]; bl[2*np][1] = t4[1];
                bl[2*np+1][0] = t4[2]; bl[2*np+1][1] = t4[3];
            }
            #pragma unroll
            for (int mt = 0; mt < 2; mt++)
                #pragma unroll
                for (int nt = 0; nt < 8; nt++) {
                    mma16816(acc[mt][nt], ah[mt], bh[nt]);
                    mma16816(acc[mt][nt], ah[mt], bl[nt]);
                    mma16816(acc[mt][nt], al[mt], bh[nt]);
                }
        }
    }
    int g = lane >> 2, t = lane & 3;
    #pragma unroll
    for (int mt = 0; mt < 2; mt++) {
        long long r0 = row0 + warpM * 32 + mt * 16 + g;
        #pragma unroll
        for (int nt = 0; nt < 8; nt++) {
            int col = warpN * 64 + nt * 8 + t * 2;
            if (r0 < M)
                *reinterpret_cast<float2*>(&g_h1[r0 * HDIM + col]) =
                    make_float2(acc[mt][nt][0], acc[mt][nt][1]);
            if (r0 + 8 < M)
                *reinterpret_cast<float2*>(&g_h1[(r0 + 8) * HDIM + col]) =
                    make_float2(acc[mt][nt][2], acc[mt][nt][3]);
        }
    }
}

// ---------------- GEMM2: h2 interleaved [M][branch*64+col] = {g1,p1}[M,128] @ W2 ----------------
static constexpr int G2_SMEM = 2 * 18432 + 2 * 9216;
__global__ void __launch_bounds__(256) k_gemm2_tc(int M) {
    extern __shared__ char smem[];
    uint32_t sb = smem_to_u32(smem);
    const int tid = threadIdx.x, wid = tid >> 5, lane = tid & 31;
    const int warpM = wid & 3, warpN = wid >> 2;          // 4 x 2 warps, warp tile 32x32
    const int AHI = 0, ALO = 18432, BHI = 36864, BLO = 46080;

    long long row0 = (long long)blockIdx.x * 128;
    int nvalid = (int)((M - row0 < 128) ? (M - row0) : 128);
    const uint4* ah4 = reinterpret_cast<const uint4*>(blockIdx.y ? g_p1h : g_g1h);
    const uint4* al4 = reinterpret_cast<const uint4*>(blockIdx.y ? g_p1l : g_g1l);
    const uint4* wh = reinterpret_cast<const uint4*>(g_w2h);
    const uint4* wl = reinterpret_cast<const uint4*>(g_w2l);
    const int cbase = blockIdx.y * ODIM;                  // interleaved column base

    float acc[2][4][4];
    #pragma unroll
    for (int i = 0; i < 2; i++)
        #pragma unroll
        for (int j = 0; j < 4; j++)
            #pragma unroll
            for (int k = 0; k < 4; k++) acc[i][j][k] = 0.0f;

    const int a_r = (lane & 7) + ((lane & 8) ? 8 : 0);
    const int a_c = (lane & 16) ? 8 : 0;
    const int b_r = (lane & 7) + ((lane & 16) ? 8 : 0);
    const int b_c = (lane & 8) ? 8 : 0;

    #pragma unroll 1
    for (int c = 0; c < 2; c++) {                         // K chunks of 64 (K=128)
        int k0u = c * 8;
        if (c) __syncthreads();
        fill_pad<128>(smem, AHI, ah4, row0, 16, k0u, nvalid, tid);
        fill_pad<128>(smem, ALO, al4, row0, 16, k0u, nvalid, tid);
        fill_pad<64>(smem, BHI, wh, 0, 16, k0u, 64, tid);
        fill_pad<64>(smem, BLO, wl, 0, 16, k0u, 64, tid);
        __syncthreads();
        #pragma unroll
        for (int k16 = 0; k16 < 4; k16++) {
            int kc = k16 * 16;
            uint32_t ah[2][4], al[2][4];
            #pragma unroll
            for (int mt = 0; mt < 2; mt++) {
                uint32_t off = (uint32_t)((warpM * 32 + mt * 16 + a_r) * 144 + (kc + a_c) * 2);
                ldmx4(ah[mt], sb + AHI + off);
                ldmx4(al[mt], sb + ALO + off);
            }
            uint32_t bh[4][2], bl[4][2];
            #pragma unroll
            for (int np = 0; np < 2; np++) {
                uint32_t off = (uint32_t)((warpN * 32 + np * 16 + b_r) * 144 + (kc + b_c) * 2);
                uint32_t t4[4];
                ldmx4(t4, sb + BHI + off);
                bh[2*np][0] = t4[0]; bh[2*np][1] = t4[1];
                bh[2*np+1][0] = t4[2]; bh[2*np+1][1] = t4[3];
                ldmx4(t4, sb + BLO + off);
                bl[2*np][0] = t4[0]; bl[2*np][1] = t4[1];
                bl[2*np+1][0] = t4[2]; bl[2*np+1][1] = t4[3];
            }
            #pragma unroll
            for (int mt = 0; mt < 2; mt++)
                #pragma unroll
                for (int nt = 0; nt < 4; nt++) {
                    mma16816(acc[mt][nt], ah[mt], bh[nt]);
                    mma16816(acc[mt][nt], ah[mt], bl[nt]);
                    mma16816(acc[mt][nt], al[mt], bh[nt]);
                }
        }
    }
    int g = lane >> 2, t = lane & 3;
    #pragma unroll
    for (int mt = 0; mt < 2; mt++) {
        long long r0 = row0 + warpM * 32 + mt * 16 + g;
        #pragma unroll
        for (int nt = 0; nt < 4; nt++) {
            int col = cbase + warpN * 32 + nt * 8 + t * 2;
            if (r0 < M)
                *reinterpret_cast<float2*>(&g_h2[r0 * 2 * ODIM + col]) =
                    make_float2(acc[mt][nt][0], acc[mt][nt][1]);
            if (r0 + 8 < M)
                *reinterpret_cast<float2*>(&g_h2[(r0 + 8) * 2 * ODIM + col]) =
                    make_float2(acc[mt][nt][2], acc[mt][nt][3]);
        }
    }
}

// ---------------- layer-1 aggregation: warp/node, both branches, emits bf16 splits ----------------
__device__ __forceinline__ void split_store(__nv_bfloat16* hi, __nv_bfloat16* lo, size_t base, float4 v) {
    __nv_bfloat16 hx = __float2bfloat16(v.x), hy = __float2bfloat16(v.y);
    __nv_bfloat16 hz = __float2bfloat16(v.z), hw = __float2bfloat16(v.w);
    __nv_bfloat162* h2 = reinterpret_cast<__nv_bfloat162*>(hi + base);
    __nv_bfloat162* l2 = reinterpret_cast<__nv_bfloat162*>(lo + base);
    h2[0] = __halves2bfloat162(hx, hy);
    h2[1] = __halves2bfloat162(hz, hw);
    l2[0] = __halves2bfloat162(__float2bfloat16(v.x - __bfloat162float(hx)),
                               __float2bfloat16(v.y - __bfloat162float(hy)));
    l2[1] = __halves2bfloat162(__float2bfloat16(v.z - __bfloat162float(hz)),
                               __float2bfloat16(v.w - __bfloat162float(hw)));
}

__global__ void k_agg1(const float* __restrict__ b1, int n) {
    int node = (blockIdx.x * blockDim.x + threadIdx.x) >> 5;
    int lane = threadIdx.x & 31;
    if (node >= n) return;
    int s0 = g_colptr[node], s1 = g_colptr[node + 1];
    float4 ag = make_float4(0, 0, 0, 0);
    float4 ap = make_float4(0, 0, 0, 0);
    int e = s0;
    for (; e + 1 < s1; e += 2) {
        int sA = g_src[e], sB = g_src[e + 1];
        float gnA = g_gn[e], pnA = g_pn[e];
        float gnB = g_gn[e + 1], pnB = g_pn[e + 1];
        float4 vA = *reinterpret_cast<const float4*>(&g_h1[(size_t)sA * HDIM + lane * 4]);
        float4 vB = *reinterpret_cast<const float4*>(&g_h1[(size_t)sB * HDIM + lane * 4]);
        ag.x += gnA * vA.x + gnB * vB.x; ag.y += gnA * vA.y + gnB * vB.y;
        ag.z += gnA * vA.z + gnB * vB.z; ag.w += gnA * vA.w + gnB * vB.w;
        ap.x += pnA * vA.x + pnB * vB.x; ap.y += pnA * vA.y + pnB * vB.y;
        ap.z += pnA * vA.z + pnB * vB.z; ap.w += pnA * vA.w + pnB * vB.w;
    }
    if (e < s1) {
        int s = g_src[e];
        float gn = g_gn[e], pn = g_pn[e];
        float4 v = *reinterpret_cast<const float4*>(&g_h1[(size_t)s * HDIM + lane * 4]);
        ag.x += gn * v.x; ag.y += gn * v.y; ag.z += gn * v.z; ag.w += gn * v.w;
        ap.x += pn * v.x; ap.y += pn * v.y; ap.z += pn * v.z; ap.w += pn * v.w;
    }
    float dg = g_disg[node]; dg *= dg;
    float dp = g_disp[node]; dp *= dp;
    float4 v = *reinterpret_cast<const float4*>(&g_h1[(size_t)node * HDIM + lane * 4]);
    ag.x += dg * v.x; ag.y += dg * v.y; ag.z += dg * v.z; ag.w += dg * v.w;
    ap.x += dp * v.x; ap.y += dp * v.y; ap.z += dp * v.z; ap.w += dp * v.w;
    float4 bb = *reinterpret_cast<const float4*>(&b1[lane * 4]);
    ag.x = fmaxf(ag.x + bb.x, 0.f); ag.y = fmaxf(ag.y + bb.y, 0.f);
    ag.z = fmaxf(ag.z + bb.z, 0.f); ag.w = fmaxf(ag.w + bb.w, 0.f);
    ap.x = fmaxf(ap.x + bb.x, 0.f); ap.y = fmaxf(ap.y + bb.y, 0.f);
    ap.z = fmaxf(ap.z + bb.z, 0.f); ap.w = fmaxf(ap.w + bb.w, 0.f);
    size_t base = (size_t)node * HDIM + lane * 4;
    split_store(g_g1h, g_g1l, base, ag);
    split_store(g_p1h, g_p1l, base, ap);
}

// ---------------- layer-2 aggregation + attention combine (interleaved h2, lane-split) ----------
// lanes 0-15 accumulate GCN branch (h2 cols 0-63), lanes 16-31 PPMI branch (cols 64-127)
__global__ void k_agg2_combine(const float* __restrict__ b2,
                               const float* __restrict__ dw,
                               const float* __restrict__ db,
                               float* __restrict__ out, int n) {
    int node = (blockIdx.x * blockDim.x + threadIdx.x) >> 5;
    int lane = threadIdx.x & 31;
    if (node >= n) return;
    int s0 = g_colptr[node], s1 = g_colptr[node + 1];
    const bool isg = lane < 16;
    float4 a = make_float4(0, 0, 0, 0);
    int e = s0;
    for (; e + 1 < s1; e += 2) {
        int sA = g_src[e], sB = g_src[e + 1];
        float wA = isg ? g_gn[e] : g_pn[e];
        float wB = isg ? g_gn[e + 1] : g_pn[e + 1];
        float4 vA = *reinterpret_cast<const float4*>(&g_h2[(size_t)sA * 2 * ODIM + lane * 4]);
        float4 vB = *reinterpret_cast<const float4*>(&g_h2[(size_t)sB * 2 * ODIM + lane * 4]);
        a.x += wA * vA.x + wB * vB.x; a.y += wA * vA.y + wB * vB.y;
        a.z += wA * vA.z + wB * vB.z; a.w += wA * vA.w + wB * vB.w;
    }
    if (e < s1) {
        int s = g_src[e];
        float w = isg ? g_gn[e] : g_pn[e];
        float4 v = *reinterpret_cast<const float4*>(&g_h2[(size_t)s * 2 * ODIM + lane * 4]);
        a.x += w * v.x; a.y += w * v.y; a.z += w * v.z; a.w += w * v.w;
    }
    float d = isg ? g_disg[node] : g_disp[node];
    d *= d;
    float4 v = *reinterpret_cast<const float4*>(&g_h2[(size_t)node * 2 * ODIM + lane * 4]);
    a.x += d * v.x; a.y += d * v.y; a.z += d * v.z; a.w += d * v.w;
    int c4 = (lane & 15) * 4;
    float4 bb = *reinterpret_cast<const float4*>(&b2[c4]);
    a.x += bb.x; a.y += bb.y; a.z += bb.z; a.w += bb.w;
    // logits per branch via masked full-warp reduction
    float4 w4 = *reinterpret_cast<const float4*>(&dw[c4]);
    float dot = a.x * w4.x + a.y * w4.y + a.z * w4.z + a.w * w4.w;
    float pg = isg ? dot : 0.0f;
    float pp = isg ? 0.0f : dot;
    #pragma unroll
    for (int o = 16; o; o >>= 1) {
        pg += __shfl_xor_sync(0xffffffffu, pg, o);
        pp += __shfl_xor_sync(0xffffffffu, pp, o);
    }
    float bd = db[0];
    float lg = pg + bd, lp = pp + bd;
    float m = fmaxf(lg, lp);
    float eg = __expf(lg - m), ep = __expf(lp - m);
    float wg = eg / (eg + ep), wp = 1.0f - wg;
    // exchange branch accumulators between half-warps
    float4 o4;
    o4.x = __shfl_xor_sync(0xffffffffu, a.x, 16);
    o4.y = __shfl_xor_sync(0xffffffffu, a.y, 16);
    o4.z = __shfl_xor_sync(0xffffffffu, a.z, 16);
    o4.w = __shfl_xor_sync(0xffffffffu, a.w, 16);
    if (isg) {
        float4 r;
        r.x = wg * a.x + wp * o4.x; r.y = wg * a.y + wp * o4.y;
        r.z = wg * a.z + wp * o4.z; r.w = wg * a.w + wp * o4.w;
        *reinterpret_cast<float4*>(&out[(size_t)node * ODIM + c4]) = r;
    }
}

// ---------------- launch ----------------
extern "C" void kernel_launch(void* const* d_in, const int* in_sizes, int n_in,
                              void* d_out, int out_size) {
    const float* x    = (const float*)d_in[0];
    const int*   ei   = (const int*)d_in[1];     // int32 [2, E]
    const float* ppmi = (const float*)d_in[2];
    const float* W1   = (const float*)d_in[3];
    const float* b1   = (const float*)d_in[4];
    const float* W2   = (const float*)d_in[5];
    const float* b2   = (const float*)d_in[6];
    const float* dw   = (const float*)d_in[7];
    const float* db   = (const float*)d_in[8];
    float*       out  = (float*)d_out;

    const int N = in_sizes[0] / DDIM;
    const int E = in_sizes[2];

    cudaFuncSetAttribute(k_gemm1_tc, cudaFuncAttributeMaxDynamicSharedMemorySize, G1_SMEM);
    cudaFuncSetAttribute(k_gemm2_tc, cudaFuncAttributeMaxDynamicSharedMemorySize, G2_SMEM);

    const int TB = 256;
    const bool fork = (g_s2 != nullptr) && (g_ev0 != nullptr) && (g_ev1 != nullptr);
    cudaStream_t sb = fork ? g_s2 : (cudaStream_t)0;

    // --- branch A (side stream when available): CSR graph build ---
    if (fork) {
        cudaEventRecord(g_ev0, 0);
        cudaStreamWaitEvent(g_s2, g_ev0, 0);
    }
    k_init<<<(N + TB - 1) / TB, TB, 0, sb>>>(N);
    k_deg<<<(E + TB - 1) / TB, TB, 0, sb>>>(ei, ppmi, E);
    k_rsqrt<<<(N + TB - 1) / TB, TB, 0, sb>>>(N);
    int nb = (N + 1023) / 1024;
    k_scan1<<<nb, 1024, 0, sb>>>(N);
    k_scan2<<<1, 128, 0, sb>>>(nb);
    k_scan3<<<nb, 1024, 0, sb>>>(N, E);
    k_fill<<<(E + TB - 1) / TB, TB, 0, sb>>>(ei, ppmi, E);
    if (fork) cudaEventRecord(g_ev1, g_s2);

    // --- branch B (capture stream): weight splits + GEMM1 (x split in-kernel) ---
    k_splitW1<<<(DDIM * HDIM + TB - 1) / TB, TB>>>(W1);
    k_splitW2<<<(HDIM * ODIM + TB - 1) / TB, TB>>>(W2);
    int g1 = (N + 127) / 128;
    k_gemm1_tc<<<g1, 256, G1_SMEM>>>(x, N);

    // --- join, then serial tail ---
    if (fork) cudaStreamWaitEvent((cudaStream_t)0, g_ev1, 0);
    k_agg1<<<(N * 32 + TB - 1) / TB, TB>>>(b1, N);
    dim3 grid2(g1, 2);
    k_gemm2_tc<<<grid2, 256, G2_SMEM>>>(N);
    k_agg2_combine<<<(N * 32 + TB - 1) / TB, TB>>>(b2, dw, db, out, N);
}